// round 10
// baseline (speedup 1.0000x reference)
#include <cuda_runtime.h>
#include <cstdint>

#define B_ 4
#define CH 512
#define PIX 4096            // 64*64
#define CONV_SCALE 0.020428760f
#define MS_SCALE   0.044194174f
#define RGB_SCALE  0.086419101f
#define LRELU_A    0.2f

// ---------------- device scratch (static; no allocation) ----------------
__device__ float g_x0[B_ * CH * PIX];          // modulated upsampled maps (conv0 input)
__device__ float g_x1[B_ * CH * PIX];          // s1-modulated h0 (conv1 input)
__device__ float g_wT[2][CH * 9 * CH];         // weights transposed: [layer][k = ci*9+kk][co]
__device__ float g_wsqT[2][CH * CH];           // [layer][ci][co] = sum_kk W^2
__device__ float g_s[3][B_ * CH];              // styles s0, s1, sr
__device__ float g_d[2][B_ * CH];              // demod factors d0, d1

// ---------------- f32x2 helpers ----------------
__device__ __forceinline__ void fma2(unsigned long long& acc, unsigned long long a,
                                     unsigned long long b) {
    asm("fma.rn.f32x2 %0, %1, %2, %0;" : "+l"(acc) : "l"(a), "l"(b));
}
__device__ __forceinline__ unsigned long long pack2(float x, float y) {
    unsigned long long r;
    asm("mov.b64 %0, {%1, %2};" : "=l"(r) : "f"(x), "f"(y));
    return r;
}
__device__ __forceinline__ float2 unpack2(unsigned long long v) {
    float2 f;
    asm("mov.b64 {%0, %1}, %2;" : "=f"(f.x), "=f"(f.y) : "l"(v));
    return f;
}

// bilinear-2x (align_corners=False / half-pixel, edge-clamped) weight helper
__device__ __forceinline__ void up_wts(int c, int& j0, int& j1, float& w0, float& w1) {
    int i = c >> 1;
    if (c & 1) { j0 = i; j1 = (i + 1 < 32) ? i + 1 : 31; w0 = 0.75f; w1 = 0.25f; }
    else       { j0 = (i > 0) ? i - 1 : 0; j1 = i;       w0 = 0.25f; w1 = 0.75f; }
}

// ---------------- styles: s[b,ci] = MS_SCALE * sum_j w[b,j]*mw[ci,j] + mb[ci] ---------
__global__ void style_kernel(const float* __restrict__ w,
                             const float* __restrict__ m0w, const float* __restrict__ m0b,
                             const float* __restrict__ m1w, const float* __restrict__ m1b,
                             const float* __restrict__ mrw, const float* __restrict__ mrb) {
    int which = blockIdx.z;
    int b = blockIdx.y;
    int ci = blockIdx.x * 128 + threadIdx.x;
    const float* mw = (which == 0) ? m0w : (which == 1) ? m1w : mrw;
    const float* mb = (which == 0) ? m0b : (which == 1) ? m1b : mrb;
    __shared__ float ws[CH];
    for (int i = threadIdx.x; i < CH; i += 128) ws[i] = w[b * CH + i];
    __syncthreads();
    const float* row = mw + (size_t)ci * CH;
    float acc = 0.f;
#pragma unroll 8
    for (int j = 0; j < CH; j++) acc += ws[j] * row[j];
    g_s[which][b * CH + ci] = acc * MS_SCALE + mb[ci];
}

// ---------------- wsqT[layer][ci][co] = sum_kk W[co][ci][kk]^2 ----------------
__global__ void wsq_kernel(const float* __restrict__ w0, const float* __restrict__ w1) {
    int layer = blockIdx.y;
    int co = blockIdx.x;
    int ci = threadIdx.x;
    const float* W = (layer ? w1 : w0) + ((size_t)co * CH + ci) * 9;
    float acc = 0.f;
#pragma unroll
    for (int k = 0; k < 9; k++) acc += W[k] * W[k];
    g_wsqT[layer][ci * CH + co] = acc;
}

// ---------------- weight transpose: [co][k] -> [k][co], k = ci*9+kk ----------------
__global__ void wtrans_kernel(const float* __restrict__ w0, const float* __restrict__ w1) {
    int layer = blockIdx.z;
    const float* in = layer ? w1 : w0;
    float* out = g_wT[layer];
    __shared__ float tile[32][33];
    int kb = blockIdx.x * 32, cob = blockIdx.y * 32;
    for (int r = threadIdx.y; r < 32; r += 8) {
        tile[r][threadIdx.x] = in[(size_t)(cob + r) * (CH * 9) + kb + threadIdx.x];
    }
    __syncthreads();
    for (int r = threadIdx.y; r < 32; r += 8) {
        out[(size_t)(kb + r) * CH + cob + threadIdx.x] = tile[threadIdx.x][r];
    }
}

// ---------------- demod: d[b,co] = rsqrt(CS^2 * sum_ci wsqT[ci][co]*s^2 + 1e-8) -------
__global__ void demod_kernel() {
    int layer = blockIdx.y;
    int b = blockIdx.x;
    int co = threadIdx.x;
    __shared__ float s2[CH];
    const float* sl = g_s[layer] + b * CH;
    for (int i = threadIdx.x; i < CH; i += blockDim.x) { float v = sl[i]; s2[i] = v * v; }
    __syncthreads();
    const float* wt = g_wsqT[layer];
    float acc = 0.f;
#pragma unroll 8
    for (int ci = 0; ci < CH; ci++) acc += wt[ci * CH + co] * s2[ci];
    g_d[layer][b * CH + co] = rsqrtf(acc * (CONV_SCALE * CONV_SCALE) + 1e-8f);
}

// ---------------- upsample 2x + modulate by s0 -> g_x0 ----------------
__global__ void upmod_kernel(const float* __restrict__ maps) {
    int ci = blockIdx.x, b = blockIdx.y;
    const float* in = maps + ((size_t)b * CH + ci) * 1024;
    float sv = g_s[0][b * CH + ci];
    __shared__ float sm[1024];
    for (int i = threadIdx.x; i < 1024; i += 256) sm[i] = in[i];
    __syncthreads();
    float* out = g_x0 + ((size_t)b * CH + ci) * PIX;
    for (int p = threadIdx.x; p < PIX; p += 256) {
        int Y = p >> 6, X = p & 63;
        int y0, y1, x0, x1; float wy0, wy1, wx0, wx1;
        up_wts(Y, y0, y1, wy0, wy1);
        up_wts(X, x0, x1, wx0, wx1);
        float v = wy0 * (wx0 * sm[y0 * 32 + x0] + wx1 * sm[y0 * 32 + x1]) +
                  wy1 * (wx0 * sm[y1 * 32 + x0] + wx1 * sm[y1 * 32 + x1]);
        out[p] = v * sv;
    }
}

// ---------------- main conv: 3x3, shared weights, f32x2 microkernel ----------------
// block tile: 128 pixels (2 rows x 64) x 128 cout ; Cin chunk = 8
// thread (16x16): 8 pixels x 8 cout (4 f32x2 pairs)
#define CK 8
template <int L>
__global__ __launch_bounds__(256, 2) void conv_kernel(const float* __restrict__ bias,
                                                      const float* __restrict__ ns,
                                                      const float* __restrict__ noise,
                                                      float* __restrict__ Yext) {
    const float* X = (L == 0) ? g_x0 : g_x1;
    const float* Wt = g_wT[L];
    float* Y = (L == 0) ? g_x1 : Yext;

    const int b = blockIdx.z;
    const int r0 = blockIdx.y * 2;
    const int coBase = blockIdx.x * 128;

    __shared__ __align__(16) float Xs[CK][4][66];
    __shared__ __align__(16) float Ws[CK][9][128];

    const int tid = threadIdx.x;
    const int tx = tid & 15;   // cout group
    const int ty = tid >> 4;   // pixel group
    const int rl = ty >> 3;            // local output row (0/1)
    const int x0p = (ty & 7) * 8;      // pixel column base

    unsigned long long acc[8][4];
#pragma unroll
    for (int i = 0; i < 8; i++)
#pragma unroll
        for (int j = 0; j < 4; j++) acc[i][j] = 0ULL;

    const float* Xb = X + (size_t)b * CH * PIX;

    for (int c0 = 0; c0 < CH; c0 += CK) {
        // ---- load input tile: rows r0-1..r0+2, cols -1..64 (zero pad) ----
        for (int i = tid; i < CK * 4 * 66; i += 256) {
            int ci = i / 264;
            int rem = i - ci * 264;
            int rr = rem / 66;
            int cc = rem - rr * 66;
            int gy = r0 - 1 + rr;
            int gx = cc - 1;
            float v = 0.f;
            if (((unsigned)gy < 64u) && ((unsigned)gx < 64u))
                v = Xb[(size_t)(c0 + ci) * PIX + gy * 64 + gx];
            Xs[ci][rr][cc] = v;
        }
        // ---- load weight tile (coalesced from transposed layout) ----
        {
            float* wsl = &Ws[0][0][0];
            const float* gsrc = Wt + (size_t)c0 * 9 * CH + coBase;
            for (int i = tid; i < CK * 9 * 128; i += 256) {
                int ci = i / 1152;
                int rem = i - ci * 1152;
                int kk = rem >> 7;
                int co = rem & 127;
                wsl[i] = gsrc[(size_t)ci * (9 * CH) + kk * CH + co];
            }
        }
        __syncthreads();

        // ---- compute ----
#pragma unroll
        for (int ci = 0; ci < CK; ci++) {
#pragma unroll
            for (int dy = 0; dy < 3; dy++) {
                const float* xrow = &Xs[ci][rl + dy][x0p];
#pragma unroll
                for (int dx = 0; dx < 3; dx++) {
                    unsigned long long ad[8];
#pragma unroll
                    for (int i = 0; i < 8; i++) {
                        float av = xrow[dx + i];
                        ad[i] = pack2(av, av);
                    }
                    const unsigned long long* wp =
                        reinterpret_cast<const unsigned long long*>(&Ws[ci][dy * 3 + dx][0]) + tx * 4;
                    unsigned long long w0 = wp[0], w1 = wp[1], w2 = wp[2], w3 = wp[3];
#pragma unroll
                    for (int i = 0; i < 8; i++) {
                        fma2(acc[i][0], ad[i], w0);
                        fma2(acc[i][1], ad[i], w1);
                        fma2(acc[i][2], ad[i], w2);
                        fma2(acc[i][3], ad[i], w3);
                    }
                }
            }
        }
        __syncthreads();
    }

    // ---- epilogue: y = lrelu(acc*d*CS + bias + ns*noise) [* s1 if L==0] ----
    const float* dmod = g_d[L] + b * CH;
    const float* snext = g_s[1] + b * CH;
    const float* noisep = noise + b * PIX;
    const int pbase = (r0 + rl) * 64 + x0p;
    const size_t outbase = (size_t)b * CH * PIX;

    float dmv[8], bbv[8], nnv[8], snv[8];
#pragma unroll
    for (int jj = 0; jj < 8; jj++) {
        int co = coBase + tx * 8 + jj;
        dmv[jj] = dmod[co] * CONV_SCALE;
        bbv[jj] = bias[co];
        nnv[jj] = ns[co];
        snv[jj] = (L == 0) ? snext[co] : 1.f;
    }
#pragma unroll
    for (int i = 0; i < 8; i++) {
        int p = pbase + i;
        float nz = noisep[p];
#pragma unroll
        for (int j = 0; j < 4; j++) {
            float2 v2 = unpack2(acc[i][j]);
            int jj0 = 2 * j, jj1 = 2 * j + 1;
            float v0 = v2.x * dmv[jj0] + bbv[jj0] + nnv[jj0] * nz;
            float v1 = v2.y * dmv[jj1] + bbv[jj1] + nnv[jj1] * nz;
            v0 = (v0 >= 0.f) ? v0 : LRELU_A * v0;
            v1 = (v1 >= 0.f) ? v1 : LRELU_A * v1;
            Y[outbase + (size_t)(coBase + tx * 8 + jj0) * PIX + p] = v0 * snv[jj0];
            Y[outbase + (size_t)(coBase + tx * 8 + jj1) * PIX + p] = v1 * snv[jj1];
        }
    }
}

// ---------------- to_rgb: rgb_out = up2(rgb) + (sum_ci wr[b,c,ci]*h) + rgb_b ---------
__global__ void torgb_kernel(const float* __restrict__ h, const float* __restrict__ rgb_in,
                             const float* __restrict__ rgb_w, const float* __restrict__ rgb_b,
                             float* __restrict__ out) {
    int b = blockIdx.y;
    int p = blockIdx.x * 256 + threadIdx.x;
    __shared__ float wr[3][CH];
    const float* sr = g_s[2] + b * CH;
    for (int i = threadIdx.x; i < 3 * CH; i += 256) {
        int c = i >> 9, ci = i & 511;
        wr[c][ci] = rgb_w[c * CH + ci] * RGB_SCALE * sr[ci];
    }
    __syncthreads();

    float a0 = 0.f, a1 = 0.f, a2 = 0.f;
    const float* hp = h + (size_t)b * CH * PIX + p;
#pragma unroll 4
    for (int ci = 0; ci < CH; ci++) {
        float hv = hp[(size_t)ci * PIX];
        a0 += wr[0][ci] * hv;
        a1 += wr[1][ci] * hv;
        a2 += wr[2][ci] * hv;
    }
    int Y = p >> 6, X = p & 63;
    int y0, y1, x0, x1; float wy0, wy1, wx0, wx1;
    up_wts(Y, y0, y1, wy0, wy1);
    up_wts(X, x0, x1, wx0, wx1);
    float accs[3] = {a0, a1, a2};
#pragma unroll
    for (int c = 0; c < 3; c++) {
        const float* rin = rgb_in + ((size_t)b * 3 + c) * 1024;
        float rup = wy0 * (wx0 * rin[y0 * 32 + x0] + wx1 * rin[y0 * 32 + x1]) +
                    wy1 * (wx0 * rin[y1 * 32 + x0] + wx1 * rin[y1 * 32 + x1]);
        out[((size_t)b * 3 + c) * PIX + p] = rup + accs[c] + rgb_b[c];
    }
}

// ---------------- launch ----------------
extern "C" void kernel_launch(void* const* d_in, const int* in_sizes, int n_in,
                              void* d_out, int out_size) {
    const float* maps    = (const float*)d_in[0];
    const float* w       = (const float*)d_in[1];
    const float* rgb     = (const float*)d_in[2];
    const float* noise0  = (const float*)d_in[3];
    const float* noise1  = (const float*)d_in[4];
    const float* conv0_w = (const float*)d_in[5];
    const float* conv0_b = (const float*)d_in[6];
    const float* ms0_w   = (const float*)d_in[7];
    const float* ms0_b   = (const float*)d_in[8];
    const float* ns0     = (const float*)d_in[9];
    const float* conv1_w = (const float*)d_in[10];
    const float* conv1_b = (const float*)d_in[11];
    const float* ms1_w   = (const float*)d_in[12];
    const float* ms1_b   = (const float*)d_in[13];
    const float* ns1     = (const float*)d_in[14];
    const float* rgb_w   = (const float*)d_in[15];
    const float* rgb_b   = (const float*)d_in[16];
    const float* msr_w   = (const float*)d_in[17];
    const float* msr_b   = (const float*)d_in[18];

    float* out = (float*)d_out;
    float* hout = out + (size_t)B_ * 3 * PIX;   // h section of the output tuple

    style_kernel<<<dim3(4, B_, 3), 128>>>(w, ms0_w, ms0_b, ms1_w, ms1_b, msr_w, msr_b);
    wsq_kernel<<<dim3(512, 2), 512>>>(conv0_w, conv1_w);
    wtrans_kernel<<<dim3(144, 16, 2), dim3(32, 8)>>>(conv0_w, conv1_w);
    demod_kernel<<<dim3(B_, 2), 512>>>();
    upmod_kernel<<<dim3(512, B_), 256>>>(maps);
    conv_kernel<0><<<dim3(4, 32, B_), 256>>>(conv0_b, ns0, noise0, nullptr);
    conv_kernel<1><<<dim3(4, 32, B_), 256>>>(conv1_b, ns1, noise1, hout);
    torgb_kernel<<<dim3(16, B_), 256>>>(hout, rgb, rgb_w, rgb_b, out);
}

// round 11
// speedup vs baseline: 1.0009x; 1.0009x over previous
#include <cuda_runtime.h>
#include <cstdint>

#define B_ 4
#define CH 512
#define PIX 4096            // 64*64
#define CONV_SCALE 0.020428760f
#define MS_SCALE   0.044194174f
#define RGB_SCALE  0.086419101f
#define LRELU_A    0.2f

// ---------------- device scratch (static; no allocation) ----------------
__device__ float g_x0[B_ * CH * PIX];          // modulated upsampled maps (conv0 input)
__device__ float g_x1[B_ * CH * PIX];          // s1-modulated h0 (conv1 input)
__device__ float g_wT[2][CH * 9 * CH];         // weights transposed: [layer][k = ci*9+kk][co]
__device__ float g_wsqT[2][CH * CH];           // [layer][ci][co] = sum_kk W^2
__device__ float g_s[3][B_ * CH];              // styles s0, s1, sr
__device__ float g_d[2][B_ * CH];              // demod factors d0, d1

// ---------------- f32x2 helpers ----------------
__device__ __forceinline__ void fma2(unsigned long long& acc, unsigned long long a,
                                     unsigned long long b) {
    asm("fma.rn.f32x2 %0, %1, %2, %0;" : "+l"(acc) : "l"(a), "l"(b));
}
__device__ __forceinline__ unsigned long long pack2(float x, float y) {
    unsigned long long r;
    asm("mov.b64 %0, {%1, %2};" : "=l"(r) : "f"(x), "f"(y));
    return r;
}
__device__ __forceinline__ float2 unpack2(unsigned long long v) {
    float2 f;
    asm("mov.b64 {%0, %1}, %2;" : "=f"(f.x), "=f"(f.y) : "l"(v));
    return f;
}

// bilinear-2x (align_corners=False / half-pixel, edge-clamped) weight helper
__device__ __forceinline__ void up_wts(int c, int& j0, int& j1, float& w0, float& w1) {
    int i = c >> 1;
    if (c & 1) { j0 = i; j1 = (i + 1 < 32) ? i + 1 : 31; w0 = 0.75f; w1 = 0.25f; }
    else       { j0 = (i > 0) ? i - 1 : 0; j1 = i;       w0 = 0.25f; w1 = 0.75f; }
}

// ---------------- styles: s[b,ci] = MS_SCALE * sum_j w[b,j]*mw[ci,j] + mb[ci] ---------
__global__ void style_kernel(const float* __restrict__ w,
                             const float* __restrict__ m0w, const float* __restrict__ m0b,
                             const float* __restrict__ m1w, const float* __restrict__ m1b,
                             const float* __restrict__ mrw, const float* __restrict__ mrb) {
    int which = blockIdx.z;
    int b = blockIdx.y;
    int ci = blockIdx.x * 128 + threadIdx.x;
    const float* mw = (which == 0) ? m0w : (which == 1) ? m1w : mrw;
    const float* mb = (which == 0) ? m0b : (which == 1) ? m1b : mrb;
    __shared__ float ws[CH];
    for (int i = threadIdx.x; i < CH; i += 128) ws[i] = w[b * CH + i];
    __syncthreads();
    const float* row = mw + (size_t)ci * CH;
    float acc = 0.f;
#pragma unroll 8
    for (int j = 0; j < CH; j++) acc += ws[j] * row[j];
    g_s[which][b * CH + ci] = acc * MS_SCALE + mb[ci];
}

// ---------------- wsqT[layer][ci][co] = sum_kk W[co][ci][kk]^2 ----------------
__global__ void wsq_kernel(const float* __restrict__ w0, const float* __restrict__ w1) {
    int layer = blockIdx.y;
    int co = blockIdx.x;
    int ci = threadIdx.x;
    const float* W = (layer ? w1 : w0) + ((size_t)co * CH + ci) * 9;
    float acc = 0.f;
#pragma unroll
    for (int k = 0; k < 9; k++) acc += W[k] * W[k];
    g_wsqT[layer][ci * CH + co] = acc;
}

// ---------------- weight transpose: [co][k] -> [k][co], k = ci*9+kk ----------------
__global__ void wtrans_kernel(const float* __restrict__ w0, const float* __restrict__ w1) {
    int layer = blockIdx.z;
    const float* in = layer ? w1 : w0;
    float* out = g_wT[layer];
    __shared__ float tile[32][33];
    int kb = blockIdx.x * 32, cob = blockIdx.y * 32;
    for (int r = threadIdx.y; r < 32; r += 8) {
        tile[r][threadIdx.x] = in[(size_t)(cob + r) * (CH * 9) + kb + threadIdx.x];
    }
    __syncthreads();
    for (int r = threadIdx.y; r < 32; r += 8) {
        out[(size_t)(kb + r) * CH + cob + threadIdx.x] = tile[threadIdx.x][r];
    }
}

// ---------------- demod: d[b,co] = rsqrt(CS^2 * sum_ci wsqT[ci][co]*s^2 + 1e-8) -------
__global__ void demod_kernel() {
    int layer = blockIdx.y;
    int b = blockIdx.x;
    int co = threadIdx.x;
    __shared__ float s2[CH];
    const float* sl = g_s[layer] + b * CH;
    for (int i = threadIdx.x; i < CH; i += blockDim.x) { float v = sl[i]; s2[i] = v * v; }
    __syncthreads();
    const float* wt = g_wsqT[layer];
    float acc = 0.f;
#pragma unroll 8
    for (int ci = 0; ci < CH; ci++) acc += wt[ci * CH + co] * s2[ci];
    g_d[layer][b * CH + co] = rsqrtf(acc * (CONV_SCALE * CONV_SCALE) + 1e-8f);
}

// ---------------- upsample 2x + modulate by s0 -> g_x0 ----------------
__global__ void upmod_kernel(const float* __restrict__ maps) {
    int ci = blockIdx.x, b = blockIdx.y;
    const float* in = maps + ((size_t)b * CH + ci) * 1024;
    float sv = g_s[0][b * CH + ci];
    __shared__ float sm[1024];
    for (int i = threadIdx.x; i < 1024; i += 256) sm[i] = in[i];
    __syncthreads();
    float* out = g_x0 + ((size_t)b * CH + ci) * PIX;
    for (int p = threadIdx.x; p < PIX; p += 256) {
        int Y = p >> 6, X = p & 63;
        int y0, y1, x0, x1; float wy0, wy1, wx0, wx1;
        up_wts(Y, y0, y1, wy0, wy1);
        up_wts(X, x0, x1, wx0, wx1);
        float v = wy0 * (wx0 * sm[y0 * 32 + x0] + wx1 * sm[y0 * 32 + x1]) +
                  wy1 * (wx0 * sm[y1 * 32 + x0] + wx1 * sm[y1 * 32 + x1]);
        out[p] = v * sv;
    }
}

// ---------------- main conv: 3x3, shared weights, f32x2 microkernel ----------------
// block tile: 128 pixels (2 rows x 64) x 128 cout ; Cin chunk = 8
// thread (16x16): 8 pixels x 8 cout (4 f32x2 pairs)
#define CK 8
template <int L>
__global__ __launch_bounds__(256, 2) void conv_kernel(const float* __restrict__ bias,
                                                      const float* __restrict__ ns,
                                                      const float* __restrict__ noise,
                                                      float* __restrict__ Yext) {
    const float* X = (L == 0) ? g_x0 : g_x1;
    const float* Wt = g_wT[L];
    float* Y = (L == 0) ? g_x1 : Yext;

    const int b = blockIdx.z;
    const int r0 = blockIdx.y * 2;
    const int coBase = blockIdx.x * 128;

    __shared__ __align__(16) float Xs[CK][4][66];
    __shared__ __align__(16) float Ws[CK][9][128];

    const int tid = threadIdx.x;
    const int tx = tid & 15;   // cout group
    const int ty = tid >> 4;   // pixel group
    const int rl = ty >> 3;            // local output row (0/1)
    const int x0p = (ty & 7) * 8;      // pixel column base

    unsigned long long acc[8][4];
#pragma unroll
    for (int i = 0; i < 8; i++)
#pragma unroll
        for (int j = 0; j < 4; j++) acc[i][j] = 0ULL;

    const float* Xb = X + (size_t)b * CH * PIX;

    for (int c0 = 0; c0 < CH; c0 += CK) {
        // ---- load input tile: rows r0-1..r0+2, cols -1..64 (zero pad) ----
        for (int i = tid; i < CK * 4 * 66; i += 256) {
            int ci = i / 264;
            int rem = i - ci * 264;
            int rr = rem / 66;
            int cc = rem - rr * 66;
            int gy = r0 - 1 + rr;
            int gx = cc - 1;
            float v = 0.f;
            if (((unsigned)gy < 64u) && ((unsigned)gx < 64u))
                v = Xb[(size_t)(c0 + ci) * PIX + gy * 64 + gx];
            Xs[ci][rr][cc] = v;
        }
        // ---- load weight tile (coalesced from transposed layout) ----
        {
            float* wsl = &Ws[0][0][0];
            const float* gsrc = Wt + (size_t)c0 * 9 * CH + coBase;
            for (int i = tid; i < CK * 9 * 128; i += 256) {
                int ci = i / 1152;
                int rem = i - ci * 1152;
                int kk = rem >> 7;
                int co = rem & 127;
                wsl[i] = gsrc[(size_t)ci * (9 * CH) + kk * CH + co];
            }
        }
        __syncthreads();

        // ---- compute ----
#pragma unroll
        for (int ci = 0; ci < CK; ci++) {
#pragma unroll
            for (int dy = 0; dy < 3; dy++) {
                const float* xrow = &Xs[ci][rl + dy][x0p];
#pragma unroll
                for (int dx = 0; dx < 3; dx++) {
                    unsigned long long ad[8];
#pragma unroll
                    for (int i = 0; i < 8; i++) {
                        float av = xrow[dx + i];
                        ad[i] = pack2(av, av);
                    }
                    const unsigned long long* wp =
                        reinterpret_cast<const unsigned long long*>(&Ws[ci][dy * 3 + dx][0]) + tx * 4;
                    unsigned long long w0 = wp[0], w1 = wp[1], w2 = wp[2], w3 = wp[3];
#pragma unroll
                    for (int i = 0; i < 8; i++) {
                        fma2(acc[i][0], ad[i], w0);
                        fma2(acc[i][1], ad[i], w1);
                        fma2(acc[i][2], ad[i], w2);
                        fma2(acc[i][3], ad[i], w3);
                    }
                }
            }
        }
        __syncthreads();
    }

    // ---- epilogue: y = lrelu(acc*d*CS + bias + ns*noise) [* s1 if L==0] ----
    const float* dmod = g_d[L] + b * CH;
    const float* snext = g_s[1] + b * CH;
    const float* noisep = noise + b * PIX;
    const int pbase = (r0 + rl) * 64 + x0p;
    const size_t outbase = (size_t)b * CH * PIX;

    float dmv[8], bbv[8], nnv[8], snv[8];
#pragma unroll
    for (int jj = 0; jj < 8; jj++) {
        int co = coBase + tx * 8 + jj;
        dmv[jj] = dmod[co] * CONV_SCALE;
        bbv[jj] = bias[co];
        nnv[jj] = ns[co];
        snv[jj] = (L == 0) ? snext[co] : 1.f;
    }
#pragma unroll
    for (int i = 0; i < 8; i++) {
        int p = pbase + i;
        float nz = noisep[p];
#pragma unroll
        for (int j = 0; j < 4; j++) {
            float2 v2 = unpack2(acc[i][j]);
            int jj0 = 2 * j, jj1 = 2 * j + 1;
            float v0 = v2.x * dmv[jj0] + bbv[jj0] + nnv[jj0] * nz;
            float v1 = v2.y * dmv[jj1] + bbv[jj1] + nnv[jj1] * nz;
            v0 = (v0 >= 0.f) ? v0 : LRELU_A * v0;
            v1 = (v1 >= 0.f) ? v1 : LRELU_A * v1;
            Y[outbase + (size_t)(coBase + tx * 8 + jj0) * PIX + p] = v0 * snv[jj0];
            Y[outbase + (size_t)(coBase + tx * 8 + jj1) * PIX + p] = v1 * snv[jj1];
        }
    }
}

// ---------------- to_rgb: rgb_out = up2(rgb) + (sum_ci wr[b,c,ci]*h) + rgb_b ---------
__global__ void torgb_kernel(const float* __restrict__ h, const float* __restrict__ rgb_in,
                             const float* __restrict__ rgb_w, const float* __restrict__ rgb_b,
                             float* __restrict__ out) {
    int b = blockIdx.y;
    int p = blockIdx.x * 256 + threadIdx.x;
    __shared__ float wr[3][CH];
    const float* sr = g_s[2] + b * CH;
    for (int i = threadIdx.x; i < 3 * CH; i += 256) {
        int c = i >> 9, ci = i & 511;
        wr[c][ci] = rgb_w[c * CH + ci] * RGB_SCALE * sr[ci];
    }
    __syncthreads();

    float a0 = 0.f, a1 = 0.f, a2 = 0.f;
    const float* hp = h + (size_t)b * CH * PIX + p;
#pragma unroll 4
    for (int ci = 0; ci < CH; ci++) {
        float hv = hp[(size_t)ci * PIX];
        a0 += wr[0][ci] * hv;
        a1 += wr[1][ci] * hv;
        a2 += wr[2][ci] * hv;
    }
    int Y = p >> 6, X = p & 63;
    int y0, y1, x0, x1; float wy0, wy1, wx0, wx1;
    up_wts(Y, y0, y1, wy0, wy1);
    up_wts(X, x0, x1, wx0, wx1);
    float accs[3] = {a0, a1, a2};
#pragma unroll
    for (int c = 0; c < 3; c++) {
        const float* rin = rgb_in + ((size_t)b * 3 + c) * 1024;
        float rup = wy0 * (wx0 * rin[y0 * 32 + x0] + wx1 * rin[y0 * 32 + x1]) +
                    wy1 * (wx0 * rin[y1 * 32 + x0] + wx1 * rin[y1 * 32 + x1]);
        out[((size_t)b * 3 + c) * PIX + p] = rup + accs[c] + rgb_b[c];
    }
}

// ---------------- launch ----------------
extern "C" void kernel_launch(void* const* d_in, const int* in_sizes, int n_in,
                              void* d_out, int out_size) {
    const float* maps    = (const float*)d_in[0];
    const float* w       = (const float*)d_in[1];
    const float* rgb     = (const float*)d_in[2];
    const float* noise0  = (const float*)d_in[3];
    const float* noise1  = (const float*)d_in[4];
    const float* conv0_w = (const float*)d_in[5];
    const float* conv0_b = (const float*)d_in[6];
    const float* ms0_w   = (const float*)d_in[7];
    const float* ms0_b   = (const float*)d_in[8];
    const float* ns0     = (const float*)d_in[9];
    const float* conv1_w = (const float*)d_in[10];
    const float* conv1_b = (const float*)d_in[11];
    const float* ms1_w   = (const float*)d_in[12];
    const float* ms1_b   = (const float*)d_in[13];
    const float* ns1     = (const float*)d_in[14];
    const float* rgb_w   = (const float*)d_in[15];
    const float* rgb_b   = (const float*)d_in[16];
    const float* msr_w   = (const float*)d_in[17];
    const float* msr_b   = (const float*)d_in[18];

    float* out = (float*)d_out;
    float* hout = out + (size_t)B_ * 3 * PIX;   // h section of the output tuple

    style_kernel<<<dim3(4, B_, 3), 128>>>(w, ms0_w, ms0_b, ms1_w, ms1_b, msr_w, msr_b);
    wsq_kernel<<<dim3(512, 2), 512>>>(conv0_w, conv1_w);
    wtrans_kernel<<<dim3(144, 16, 2), dim3(32, 8)>>>(conv0_w, conv1_w);
    demod_kernel<<<dim3(B_, 2), 512>>>();
    upmod_kernel<<<dim3(512, B_), 256>>>(maps);
    conv_kernel<0><<<dim3(4, 32, B_), 256>>>(conv0_b, ns0, noise0, nullptr);
    conv_kernel<1><<<dim3(4, 32, B_), 256>>>(conv1_b, ns1, noise1, hout);
    torgb_kernel<<<dim3(16, B_), 256>>>(hout, rgb, rgb_w, rgb_b, out);
}

// round 15
// speedup vs baseline: 2.2826x; 2.2806x over previous
#include <cuda_runtime.h>
#include <cuda_bf16.h>
#include <cstdint>

#define B_ 4
#define CH 512
#define PIX 4096            // 64*64
#define KTOT 4608           // 9*512
#define CONV_SCALE 0.020428760f
#define MS_SCALE   0.044194174f
#define RGB_SCALE  0.086419101f
#define LRELU_A    0.2f

// ---------------- device scratch (static; zero-init => pads stay zero) ----------------
__device__ __nv_bfloat16 g_a0hi[B_ * 66 * 66 * CH];
__device__ __nv_bfloat16 g_a0lo[B_ * 66 * 66 * CH];
__device__ __nv_bfloat16 g_a1hi[B_ * 66 * 66 * CH];
__device__ __nv_bfloat16 g_a1lo[B_ * 66 * 66 * CH];
__device__ __nv_bfloat16 g_wbhi[2][CH * KTOT];   // [layer][co*4608 + tap*512 + ci]
__device__ __nv_bfloat16 g_wblo[2][CH * KTOT];
__device__ float g_wsqT[2][CH * CH];             // [layer][ci*CH + co]
__device__ float g_s[3][B_ * CH];                // styles s0, s1, sr
__device__ float g_d[2][B_ * CH];                // demod factors

// ---------------- helpers ----------------
__device__ __forceinline__ uint32_t smem_u32(const void* p) {
    uint32_t a;
    asm("{ .reg .u64 t; cvta.to.shared.u64 t, %1; cvt.u32.u64 %0, t; }" : "=r"(a) : "l"(p));
    return a;
}
#define SWZ64(x) ((x) ^ (((x) >> 3) & 0x30))

__device__ __forceinline__ void cp16(uint32_t dst, const void* src) {
    asm volatile("cp.async.cg.shared.global [%0], [%1], 16;" :: "r"(dst), "l"(src));
}
__device__ __forceinline__ void cp_commit() { asm volatile("cp.async.commit_group;" ::: "memory"); }
template <int N>
__device__ __forceinline__ void cp_wait() {
    asm volatile("cp.async.wait_group %0;" :: "n"(N) : "memory");
}

__device__ __forceinline__ void ldsm4(uint32_t* r, uint32_t addr) {
    asm volatile("ldmatrix.sync.aligned.m8n8.x4.shared.b16 {%0,%1,%2,%3}, [%4];"
                 : "=r"(r[0]), "=r"(r[1]), "=r"(r[2]), "=r"(r[3]) : "r"(addr));
}
__device__ __forceinline__ void mma16816(float* d, const uint32_t* a, const uint32_t* b) {
    asm volatile(
        "mma.sync.aligned.m16n8k16.row.col.f32.bf16.bf16.f32 "
        "{%0,%1,%2,%3}, {%4,%5,%6,%7}, {%8,%9}, {%0,%1,%2,%3};"
        : "+f"(d[0]), "+f"(d[1]), "+f"(d[2]), "+f"(d[3])
        : "r"(a[0]), "r"(a[1]), "r"(a[2]), "r"(a[3]), "r"(b[0]), "r"(b[1]));
}

// bilinear-2x (half-pixel, edge-clamped) weights
__device__ __forceinline__ void up_wts(int c, int& j0, int& j1, float& w0, float& w1) {
    int i = c >> 1;
    if (c & 1) { j0 = i; j1 = (i + 1 < 32) ? i + 1 : 31; w0 = 0.75f; w1 = 0.25f; }
    else       { j0 = (i > 0) ? i - 1 : 0; j1 = i;       w0 = 0.25f; w1 = 0.75f; }
}

__device__ __forceinline__ void bf16split(float v, __nv_bfloat16& h, __nv_bfloat16& l) {
    h = __float2bfloat16(v);
    l = __float2bfloat16(v - __bfloat162float(h));
}
__device__ __forceinline__ uint32_t packbf2(__nv_bfloat16 a, __nv_bfloat16 b) {
    uint32_t r;
    uint16_t ua = *reinterpret_cast<uint16_t*>(&a);
    uint16_t ub = *reinterpret_cast<uint16_t*>(&b);
    r = (uint32_t)ua | ((uint32_t)ub << 16);
    return r;
}

// ---------------- styles ----------------
__global__ void style_kernel(const float* __restrict__ w,
                             const float* __restrict__ m0w, const float* __restrict__ m0b,
                             const float* __restrict__ m1w, const float* __restrict__ m1b,
                             const float* __restrict__ mrw, const float* __restrict__ mrb) {
    int which = blockIdx.z, b = blockIdx.y;
    int cib = blockIdx.x * 64;
    const float* mw = (which == 0) ? m0w : (which == 1) ? m1w : mrw;
    const float* mb = (which == 0) ? m0b : (which == 1) ? m1b : mrb;
    __shared__ float ws[CH];
    int tid = threadIdx.x, lane = tid & 31, warp = tid >> 5;
    for (int i = tid; i < CH; i += 256) ws[i] = w[b * CH + i];
    __syncthreads();
#pragma unroll
    for (int q = 0; q < 8; q++) {
        int ci = cib + warp + q * 8;
        const float* row = mw + (size_t)ci * CH;
        float a = 0.f;
#pragma unroll 4
        for (int j = lane; j < CH; j += 32) a += ws[j] * row[j];
#pragma unroll
        for (int o = 16; o; o >>= 1) a += __shfl_xor_sync(~0u, a, o);
        if (lane == 0) g_s[which][b * CH + ci] = a * MS_SCALE + mb[ci];
    }
}

// ---------------- weight prep: transpose to [co][tap*512+ci], bf16 split; fused wsq -----
__global__ void wprep_kernel(const float* __restrict__ w0, const float* __restrict__ w1) {
    int layer = blockIdx.y, co = blockIdx.x, tid = threadIdx.x;
    const float* src = (layer ? w1 : w0) + (size_t)co * KTOT;
    __shared__ float buf[KTOT];
    for (int i = tid; i < KTOT; i += 256) buf[i] = src[i];
    __syncthreads();
    __nv_bfloat16* dhi = g_wbhi[layer] + (size_t)co * KTOT;
    __nv_bfloat16* dlo = g_wblo[layer] + (size_t)co * KTOT;
    for (int i = tid; i < KTOT; i += 256) {
        int kk = i >> 9, ci = i & 511;
        __nv_bfloat16 h, l;
        bf16split(buf[ci * 9 + kk], h, l);
        dhi[i] = h; dlo[i] = l;
    }
    for (int ci = tid; ci < CH; ci += 256) {
        float acc = 0.f;
#pragma unroll
        for (int k = 0; k < 9; k++) { float v = buf[ci * 9 + k]; acc += v * v; }
        g_wsqT[layer][ci * CH + co] = acc;
    }
}

// ---------------- demod ----------------
__global__ void demod_kernel() {
    int layer = blockIdx.z, b = blockIdx.y;
    int co = blockIdx.x * 64 + (threadIdx.x & 63);
    int slice = threadIdx.x >> 6;
    __shared__ float s2[CH];
    __shared__ float red[256];
    const float* sl = g_s[layer] + b * CH;
    for (int i = threadIdx.x; i < CH; i += 256) { float v = sl[i]; s2[i] = v * v; }
    __syncthreads();
    const float* wt = g_wsqT[layer];
    float acc = 0.f;
#pragma unroll 8
    for (int ci = slice * 128; ci < slice * 128 + 128; ci++) acc += wt[ci * CH + co] * s2[ci];
    red[threadIdx.x] = acc;
    __syncthreads();
    if (slice == 0) {
        float t = red[threadIdx.x] + red[threadIdx.x + 64] + red[threadIdx.x + 128] +
                  red[threadIdx.x + 192];
        g_d[layer][b * CH + co] = rsqrtf(t * (CONV_SCALE * CONV_SCALE) + 1e-8f);
    }
}

// ---------------- upsample 2x + modulate s0 -> NHWC padded bf16 hi/lo ----------------
__global__ void upmod_kernel(const float* __restrict__ maps) {
    int y = blockIdx.x, b = blockIdx.y, tid = threadIdx.x;
    int y0, y1; float wy0, wy1;
    up_wts(y, y0, y1, wy0, wy1);
    __shared__ float s[2][64][33];
    for (int cic = 0; cic < 8; cic++) {
        for (int idx = tid; idx < 4096; idx += 256) {
            int r = idx >> 11, ci = (idx >> 5) & 63, xc = idx & 31;
            int ys = r ? y1 : y0;
            s[r][ci][xc] = maps[(((size_t)b * CH + cic * 64 + ci) * 32 + ys) * 32 + xc];
        }
        __syncthreads();
        int ci = tid & 63, xq = tid >> 6;
        float sv = g_s[0][b * CH + cic * 64 + ci];
        for (int xx = xq; xx < 64; xx += 4) {
            int x0, x1; float wx0, wx1;
            up_wts(xx, x0, x1, wx0, wx1);
            float v = wy0 * (wx0 * s[0][ci][x0] + wx1 * s[0][ci][x1]) +
                      wy1 * (wx0 * s[1][ci][x0] + wx1 * s[1][ci][x1]);
            v *= sv;
            __nv_bfloat16 h, l;
            bf16split(v, h, l);
            size_t addr = (((size_t)(b * 66 + y + 1)) * 66 + (xx + 1)) * CH + cic * 64 + ci;
            g_a0hi[addr] = h;
            g_a0lo[addr] = l;
        }
        __syncthreads();
    }
}

// ---------------- HMMA conv: CTA 128px x 128co, warp m64n32, K-chunk 32, 3-pass --------
#define NC 144                 // 9 taps * 16 ci-chunks of 32
#define AHI 0
#define ALO 8192
#define BHI 16384
#define BLO 24576
#define BUFSZ 32768
#define SMEM_CONV (2 * BUFSZ)

template <int L>
__global__ void __launch_bounds__(256, 2) conv_mma(const float* __restrict__ bias,
                                                   const float* __restrict__ ns,
                                                   const float* __restrict__ noise,
                                                   float* __restrict__ Yext) {
    extern __shared__ __align__(1024) char smem_raw[];
    const uint32_t sb = smem_u32(smem_raw);

    const int tid = threadIdx.x;
    const int lane = tid & 31;
    const int wid = tid >> 5;
    const int b = blockIdx.z;
    const int y0 = blockIdx.y * 2;        // 2 image rows = 128 px
    const int co0 = blockIdx.x * 128;

    const __nv_bfloat16* Ahi = (L == 0) ? g_a0hi : g_a1hi;
    const __nv_bfloat16* Alo = (L == 0) ? g_a0lo : g_a1lo;
    const __nv_bfloat16* Whi = g_wbhi[L];
    const __nv_bfloat16* Wlo = g_wblo[L];

    // ---- fill coordinates ----
    const int frow = tid >> 1;                 // tile row (A: px, B: co)
    const int fseg0 = (tid & 1) * 2;           // two 16B segments
    const int iy = y0 + (frow >> 6);
    const int ix = frow & 63;

    // ---- ldmatrix address prep ----
    const int warp_m = (wid & 1) * 64;
    const int warp_n = (wid >> 1) * 32;
    const int a_row_l = ((lane >> 3) & 1) * 8 + (lane & 7);
    const int a_cs = lane >> 4;               // 0/1
    const int b_row_l = ((lane >> 4) & 1) * 8 + (lane & 7);
    const int b_cs = (lane >> 3) & 1;

    uint32_t arb[4]; int axr[4];
#pragma unroll
    for (int mf = 0; mf < 4; mf++) {
        int row = warp_m + mf * 16 + a_row_l;
        arb[mf] = row * 64;
        axr[mf] = (row >> 1) & 3;
    }
    uint32_t brb[2]; int bxr[2];
#pragma unroll
    for (int q = 0; q < 2; q++) {
        int row = warp_n + q * 16 + b_row_l;
        brb[q] = row * 64;
        bxr[q] = (row >> 1) & 3;
    }

    float acc[4][4][4];
#pragma unroll
    for (int i = 0; i < 4; i++)
#pragma unroll
        for (int j = 0; j < 4; j++)
#pragma unroll
            for (int e = 0; e < 4; e++) acc[i][j][e] = 0.f;

    auto do_fill = [&](int s, uint32_t bufb) {
        int tap = s >> 4, ci0 = (s & 15) * 32;
        int dy = tap / 3, dx = tap - dy * 3;
        const size_t abase = (((size_t)(b * 66 + iy + dy)) * 66 + (ix + dx)) * CH + ci0;
        const size_t wbase = ((size_t)(co0 + frow)) * KTOT + tap * 512 + ci0;
#pragma unroll
        for (int i = 0; i < 2; i++) {
            int seg = fseg0 + i;
            uint32_t off = SWZ64((uint32_t)(frow * 64 + seg * 16));
            cp16(bufb + AHI + off, Ahi + abase + seg * 8);
            cp16(bufb + ALO + off, Alo + abase + seg * 8);
            cp16(bufb + BHI + off, Whi + wbase + seg * 8);
            cp16(bufb + BLO + off, Wlo + wbase + seg * 8);
        }
        cp_commit();
    };

    do_fill(0, sb);

    for (int s = 0; s < NC; s++) {
        uint32_t bb = sb + (s & 1) * BUFSZ;
        if (s + 1 < NC) {
            do_fill(s + 1, sb + ((s + 1) & 1) * BUFSZ);
            cp_wait<1>();
        } else {
            cp_wait<0>();
        }
        __syncthreads();

#pragma unroll
        for (int ks = 0; ks < 2; ks++) {
            uint32_t a[4][4], bf[2][4];
            // pass 1: Ahi x Bhi
#pragma unroll
            for (int mf = 0; mf < 4; mf++) {
                int c = ks * 2 + a_cs;
                ldsm4(a[mf], bb + AHI + arb[mf] + ((uint32_t)(c ^ axr[mf]) << 4));
            }
#pragma unroll
            for (int q = 0; q < 2; q++) {
                int c = ks * 2 + b_cs;
                ldsm4(bf[q], bb + BHI + brb[q] + ((uint32_t)(c ^ bxr[q]) << 4));
            }
#pragma unroll
            for (int mf = 0; mf < 4; mf++)
#pragma unroll
                for (int nf = 0; nf < 4; nf++)
                    mma16816(acc[mf][nf], a[mf], &bf[nf >> 1][(nf & 1) * 2]);
            // pass 2: Ahi x Blo
#pragma unroll
            for (int q = 0; q < 2; q++) {
                int c = ks * 2 + b_cs;
                ldsm4(bf[q], bb + BLO + brb[q] + ((uint32_t)(c ^ bxr[q]) << 4));
            }
#pragma unroll
            for (int mf = 0; mf < 4; mf++)
#pragma unroll
                for (int nf = 0; nf < 4; nf++)
                    mma16816(acc[mf][nf], a[mf], &bf[nf >> 1][(nf & 1) * 2]);
            // pass 3: Alo x Bhi
#pragma unroll
            for (int mf = 0; mf < 4; mf++) {
                int c = ks * 2 + a_cs;
                ldsm4(a[mf], bb + ALO + arb[mf] + ((uint32_t)(c ^ axr[mf]) << 4));
            }
#pragma unroll
            for (int q = 0; q < 2; q++) {
                int c = ks * 2 + b_cs;
                ldsm4(bf[q], bb + BHI + brb[q] + ((uint32_t)(c ^ bxr[q]) << 4));
            }
#pragma unroll
            for (int mf = 0; mf < 4; mf++)
#pragma unroll
                for (int nf = 0; nf < 4; nf++)
                    mma16816(acc[mf][nf], a[mf], &bf[nf >> 1][(nf & 1) * 2]);
        }
        __syncthreads();
    }

    // ---- epilogue ----
    const float* dmod = g_d[L] + b * CH;
    const float* s1 = g_s[1] + b * CH;
    float dm[4][2], bv[4][2], nv[4][2], sv[4][2];
#pragma unroll
    for (int nf = 0; nf < 4; nf++)
#pragma unroll
        for (int j = 0; j < 2; j++) {
            int co = co0 + warp_n + nf * 8 + (lane & 3) * 2 + j;
            dm[nf][j] = dmod[co] * CONV_SCALE;
            bv[nf][j] = bias[co];
            nv[nf][j] = ns[co];
            sv[nf][j] = (L == 0) ? s1[co] : 1.f;
        }

#pragma unroll
    for (int mf = 0; mf < 4; mf++)
#pragma unroll
        for (int h = 0; h < 2; h++) {
            int m = warp_m + mf * 16 + (lane >> 2) + h * 8;
            int py = y0 + (m >> 6), px = m & 63;
            int p = py * 64 + px;
            float nz = noise[b * PIX + p];
#pragma unroll
            for (int nf = 0; nf < 4; nf++) {
                float v0 = acc[mf][nf][h * 2 + 0] * dm[nf][0] + bv[nf][0] + nv[nf][0] * nz;
                float v1 = acc[mf][nf][h * 2 + 1] * dm[nf][1] + bv[nf][1] + nv[nf][1] * nz;
                v0 = (v0 >= 0.f) ? v0 : LRELU_A * v0;
                v1 = (v1 >= 0.f) ? v1 : LRELU_A * v1;
                int co = co0 + warp_n + nf * 8 + (lane & 3) * 2;
                if (L == 0) {
                    float m0 = v0 * sv[nf][0], m1 = v1 * sv[nf][1];
                    __nv_bfloat16 h0, l0, h1, l1;
                    bf16split(m0, h0, l0);
                    bf16split(m1, h1, l1);
                    size_t addr = (((size_t)(b * 66 + py + 1)) * 66 + (px + 1)) * CH + co;
                    *reinterpret_cast<uint32_t*>(&g_a1hi[addr]) = packbf2(h0, h1);
                    *reinterpret_cast<uint32_t*>(&g_a1lo[addr]) = packbf2(l0, l1);
                } else {
                    Yext[((size_t)b * CH + co) * PIX + p] = v0;
                    Yext[((size_t)b * CH + co + 1) * PIX + p] = v1;
                }
            }
        }
}

// ---------------- to_rgb ----------------
__global__ void torgb_kernel(const float* __restrict__ h, const float* __restrict__ rgb_in,
                             const float* __restrict__ rgb_w, const float* __restrict__ rgb_b,
                             float* __restrict__ out) {
    int b = blockIdx.y;
    int p = blockIdx.x * 256 + threadIdx.x;
    __shared__ float wr[3][CH];
    const float* sr = g_s[2] + b * CH;
    for (int i = threadIdx.x; i < 3 * CH; i += 256) {
        int c = i >> 9, ci = i & 511;
        wr[c][ci] = rgb_w[c * CH + ci] * RGB_SCALE * sr[ci];
    }
    __syncthreads();

    float a0 = 0.f, a1 = 0.f, a2 = 0.f;
    const float* hp = h + (size_t)b * CH * PIX + p;
#pragma unroll 8
    for (int ci = 0; ci < CH; ci++) {
        float hv = hp[(size_t)ci * PIX];
        a0 += wr[0][ci] * hv;
        a1 += wr[1][ci] * hv;
        a2 += wr[2][ci] * hv;
    }
    int Y = p >> 6, X = p & 63;
    int y0, y1, x0, x1; float wy0, wy1, wx0, wx1;
    up_wts(Y, y0, y1, wy0, wy1);
    up_wts(X, x0, x1, wx0, wx1);
    float accs[3] = {a0, a1, a2};
#pragma unroll
    for (int c = 0; c < 3; c++) {
        const float* rin = rgb_in + ((size_t)b * 3 + c) * 1024;
        float rup = wy0 * (wx0 * rin[y0 * 32 + x0] + wx1 * rin[y0 * 32 + x1]) +
                    wy1 * (wx0 * rin[y1 * 32 + x0] + wx1 * rin[y1 * 32 + x1]);
        out[((size_t)b * 3 + c) * PIX + p] = rup + accs[c] + rgb_b[c];
    }
}

// ---------------- launch ----------------
extern "C" void kernel_launch(void* const* d_in, const int* in_sizes, int n_in,
                              void* d_out, int out_size) {
    const float* maps    = (const float*)d_in[0];
    const float* w       = (const float*)d_in[1];
    const float* rgb     = (const float*)d_in[2];
    const float* noise0  = (const float*)d_in[3];
    const float* noise1  = (const float*)d_in[4];
    const float* conv0_w = (const float*)d_in[5];
    const float* conv0_b = (const float*)d_in[6];
    const float* ms0_w   = (const float*)d_in[7];
    const float* ms0_b   = (const float*)d_in[8];
    const float* ns0     = (const float*)d_in[9];
    const float* conv1_w = (const float*)d_in[10];
    const float* conv1_b = (const float*)d_in[11];
    const float* ms1_w   = (const float*)d_in[12];
    const float* ms1_b   = (const float*)d_in[13];
    const float* ns1     = (const float*)d_in[14];
    const float* rgb_w   = (const float*)d_in[15];
    const float* rgb_b   = (const float*)d_in[16];
    const float* msr_w   = (const float*)d_in[17];
    const float* msr_b   = (const float*)d_in[18];

    float* out = (float*)d_out;
    float* hout = out + (size_t)B_ * 3 * PIX;

    cudaFuncSetAttribute(conv_mma<0>, cudaFuncAttributeMaxDynamicSharedMemorySize, SMEM_CONV);
    cudaFuncSetAttribute(conv_mma<1>, cudaFuncAttributeMaxDynamicSharedMemorySize, SMEM_CONV);

    style_kernel<<<dim3(8, B_, 3), 256>>>(w, ms0_w, ms0_b, ms1_w, ms1_b, msr_w, msr_b);
    wprep_kernel<<<dim3(512, 2), 256>>>(conv0_w, conv1_w);
    demod_kernel<<<dim3(8, B_, 2), 256>>>();
    upmod_kernel<<<dim3(64, B_), 256>>>(maps);
    conv_mma<0><<<dim3(4, 32, B_), 256, SMEM_CONV>>>(conv0_b, ns0, noise0, nullptr);
    conv_mma<1><<<dim3(4, 32, B_), 256, SMEM_CONV>>>(conv1_b, ns1, noise1, hout);
    torgb_kernel<<<dim3(16, B_), 256>>>(hout, rgb, rgb_w, rgb_b, out);
}

// round 16
// speedup vs baseline: 3.2169x; 1.4093x over previous
#include <cuda_runtime.h>
#include <cuda_fp16.h>
#include <cstdint>

#define B_ 4
#define CH 512
#define PIX 4096            // 64*64
#define KTOT 4608           // 9*512
#define CONV_SCALE 0.020428760f
#define MS_SCALE   0.044194174f
#define RGB_SCALE  0.086419101f
#define LRELU_A    0.2f

// ---------------- device scratch (static; zero-init => pads stay zero) ----------------
__device__ __half g_a0[B_ * 66 * 66 * CH];       // fp16 activations, NHWC w/ 1px halo
__device__ __half g_a1[B_ * 66 * 66 * CH];
__device__ __half g_whi[2][CH * KTOT];           // [layer][co*4608 + tap*512 + ci] fp16 hi
__device__ __half g_wlo[2][CH * KTOT];           // fp16 residual
__device__ float g_wsqT[2][CH * CH];             // [layer][ci*CH + co]
__device__ float g_s[3][B_ * CH];                // styles s0, s1, sr
__device__ float g_d[2][B_ * CH];                // demod factors

// ---------------- helpers ----------------
__device__ __forceinline__ uint32_t smem_u32(const void* p) {
    uint32_t a;
    asm("{ .reg .u64 t; cvta.to.shared.u64 t, %1; cvt.u32.u64 %0, t; }" : "=r"(a) : "l"(p));
    return a;
}
#define SWZ128(x) ((x) ^ (((x) >> 3) & 0x70))

__device__ __forceinline__ void cp16(uint32_t dst, const void* src) {
    asm volatile("cp.async.cg.shared.global [%0], [%1], 16;" :: "r"(dst), "l"(src));
}
__device__ __forceinline__ void cp_commit() { asm volatile("cp.async.commit_group;" ::: "memory"); }
template <int N>
__device__ __forceinline__ void cp_wait() {
    asm volatile("cp.async.wait_group %0;" :: "n"(N) : "memory");
}

__device__ __forceinline__ void ldsm4(uint32_t* r, uint32_t addr) {
    asm volatile("ldmatrix.sync.aligned.m8n8.x4.shared.b16 {%0,%1,%2,%3}, [%4];"
                 : "=r"(r[0]), "=r"(r[1]), "=r"(r[2]), "=r"(r[3]) : "r"(addr));
}
__device__ __forceinline__ void mma16816(float* d, const uint32_t* a, const uint32_t* b) {
    asm volatile(
        "mma.sync.aligned.m16n8k16.row.col.f32.f16.f16.f32 "
        "{%0,%1,%2,%3}, {%4,%5,%6,%7}, {%8,%9}, {%0,%1,%2,%3};"
        : "+f"(d[0]), "+f"(d[1]), "+f"(d[2]), "+f"(d[3])
        : "r"(a[0]), "r"(a[1]), "r"(a[2]), "r"(a[3]), "r"(b[0]), "r"(b[1]));
}

// bilinear-2x (half-pixel, edge-clamped) weights
__device__ __forceinline__ void up_wts(int c, int& j0, int& j1, float& w0, float& w1) {
    int i = c >> 1;
    if (c & 1) { j0 = i; j1 = (i + 1 < 32) ? i + 1 : 31; w0 = 0.75f; w1 = 0.25f; }
    else       { j0 = (i > 0) ? i - 1 : 0; j1 = i;       w0 = 0.25f; w1 = 0.75f; }
}

__device__ __forceinline__ void f16split(float v, __half& h, __half& l) {
    h = __float2half_rn(v);
    l = __float2half_rn(v - __half2float(h));
}
__device__ __forceinline__ uint32_t packh2(__half a, __half b) {
    uint16_t ua = *reinterpret_cast<uint16_t*>(&a);
    uint16_t ub = *reinterpret_cast<uint16_t*>(&b);
    return (uint32_t)ua | ((uint32_t)ub << 16);
}

// ---------------- styles ----------------
__global__ void style_kernel(const float* __restrict__ w,
                             const float* __restrict__ m0w, const float* __restrict__ m0b,
                             const float* __restrict__ m1w, const float* __restrict__ m1b,
                             const float* __restrict__ mrw, const float* __restrict__ mrb) {
    int which = blockIdx.z, b = blockIdx.y;
    int cib = blockIdx.x * 64;
    const float* mw = (which == 0) ? m0w : (which == 1) ? m1w : mrw;
    const float* mb = (which == 0) ? m0b : (which == 1) ? m1b : mrb;
    __shared__ float ws[CH];
    int tid = threadIdx.x, lane = tid & 31, warp = tid >> 5;
    for (int i = tid; i < CH; i += 256) ws[i] = w[b * CH + i];
    __syncthreads();
#pragma unroll
    for (int q = 0; q < 8; q++) {
        int ci = cib + warp + q * 8;
        const float* row = mw + (size_t)ci * CH;
        float a = 0.f;
#pragma unroll 4
        for (int j = lane; j < CH; j += 32) a += ws[j] * row[j];
#pragma unroll
        for (int o = 16; o; o >>= 1) a += __shfl_xor_sync(~0u, a, o);
        if (lane == 0) g_s[which][b * CH + ci] = a * MS_SCALE + mb[ci];
    }
}

// ---------------- weight prep: transpose to [co][tap*512+ci], fp16 split; fused wsq -----
__global__ void wprep_kernel(const float* __restrict__ w0, const float* __restrict__ w1) {
    int layer = blockIdx.y, co = blockIdx.x, tid = threadIdx.x;
    const float* src = (layer ? w1 : w0) + (size_t)co * KTOT;
    __shared__ float buf[KTOT];
    for (int i = tid; i < KTOT; i += 256) buf[i] = src[i];
    __syncthreads();
    __half* dhi = g_whi[layer] + (size_t)co * KTOT;
    __half* dlo = g_wlo[layer] + (size_t)co * KTOT;
    for (int i = tid; i < KTOT; i += 256) {
        int kk = i >> 9, ci = i & 511;
        __half h, l;
        f16split(buf[ci * 9 + kk], h, l);
        dhi[i] = h; dlo[i] = l;
    }
    for (int ci = tid; ci < CH; ci += 256) {
        float acc = 0.f;
#pragma unroll
        for (int k = 0; k < 9; k++) { float v = buf[ci * 9 + k]; acc += v * v; }
        g_wsqT[layer][ci * CH + co] = acc;
    }
}

// ---------------- demod ----------------
__global__ void demod_kernel() {
    int layer = blockIdx.z, b = blockIdx.y;
    int co = blockIdx.x * 64 + (threadIdx.x & 63);
    int slice = threadIdx.x >> 6;
    __shared__ float s2[CH];
    __shared__ float red[256];
    const float* sl = g_s[layer] + b * CH;
    for (int i = threadIdx.x; i < CH; i += 256) { float v = sl[i]; s2[i] = v * v; }
    __syncthreads();
    const float* wt = g_wsqT[layer];
    float acc = 0.f;
#pragma unroll 8
    for (int ci = slice * 128; ci < slice * 128 + 128; ci++) acc += wt[ci * CH + co] * s2[ci];
    red[threadIdx.x] = acc;
    __syncthreads();
    if (slice == 0) {
        float t = red[threadIdx.x] + red[threadIdx.x + 64] + red[threadIdx.x + 128] +
                  red[threadIdx.x + 192];
        g_d[layer][b * CH + co] = rsqrtf(t * (CONV_SCALE * CONV_SCALE) + 1e-8f);
    }
}

// ---------------- upsample 2x + modulate s0 -> NHWC padded fp16 ----------------
// grid (64 y, 8 cic, B_)
__global__ void upmod_kernel(const float* __restrict__ maps) {
    int y = blockIdx.x, cic = blockIdx.y, b = blockIdx.z, tid = threadIdx.x;
    int y0, y1; float wy0, wy1;
    up_wts(y, y0, y1, wy0, wy1);
    __shared__ float s[2][64][33];
    for (int idx = tid; idx < 4096; idx += 256) {
        int r = idx >> 11, ci = (idx >> 5) & 63, xc = idx & 31;
        int ys = r ? y1 : y0;
        s[r][ci][xc] = maps[(((size_t)b * CH + cic * 64 + ci) * 32 + ys) * 32 + xc];
    }
    __syncthreads();
    int ci = tid & 63, xq = tid >> 6;
    float sv = g_s[0][b * CH + cic * 64 + ci];
#pragma unroll
    for (int xx = xq; xx < 64; xx += 4) {
        int x0, x1; float wx0, wx1;
        up_wts(xx, x0, x1, wx0, wx1);
        float v = wy0 * (wx0 * s[0][ci][x0] + wx1 * s[0][ci][x1]) +
                  wy1 * (wx0 * s[1][ci][x0] + wx1 * s[1][ci][x1]);
        size_t addr = (((size_t)(b * 66 + y + 1)) * 66 + (xx + 1)) * CH + cic * 64 + ci;
        g_a0[addr] = __float2half_rn(v * sv);
    }
}

// ---------------- HMMA conv: CTA 128px x 128co, warp m64n32, K-chunk 64, fp16 2-pass ----
#define NC 72                  // 9 taps * 8 ci-chunks of 64
#define A_OFF 0
#define BH_OFF 16384
#define BL_OFF 32768
#define BUFSZ 49152
#define SMEM_CONV (2 * BUFSZ)

template <int L>
__global__ void __launch_bounds__(256, 2) conv_mma(const float* __restrict__ bias,
                                                   const float* __restrict__ ns,
                                                   const float* __restrict__ noise,
                                                   float* __restrict__ Yext) {
    extern __shared__ __align__(1024) char smem_raw[];
    const uint32_t sb = smem_u32(smem_raw);

    const int tid = threadIdx.x;
    const int lane = tid & 31;
    const int wid = tid >> 5;
    const int b = blockIdx.z;
    const int y0 = blockIdx.y * 2;        // 2 image rows = 128 px
    const int co0 = blockIdx.x * 128;

    const __half* A  = (L == 0) ? g_a0 : g_a1;
    const __half* Wh = g_whi[L];
    const __half* Wl = g_wlo[L];

    // ---- fill coordinates: each thread: row tid/2, 4 of the 8 16B chunks ----
    const int frow = tid >> 1;
    const int fseg0 = (tid & 1) * 4;
    const int iy = y0 + (frow >> 6);
    const int ix = frow & 63;

    // ---- ldmatrix address prep ----
    const int warp_m = (wid & 1) * 64;
    const int warp_n = (wid >> 1) * 32;
    const int a_row_l = ((lane >> 3) & 1) * 8 + (lane & 7);
    const int a_cs = lane >> 4;               // 0/1
    const int b_row_l = ((lane >> 4) & 1) * 8 + (lane & 7);
    const int b_cs = (lane >> 3) & 1;

    uint32_t arb[4]; int axr[4];
#pragma unroll
    for (int mf = 0; mf < 4; mf++) {
        int row = warp_m + mf * 16 + a_row_l;
        arb[mf] = row * 128;
        axr[mf] = row & 7;
    }
    uint32_t brb[2]; int bxr[2];
#pragma unroll
    for (int q = 0; q < 2; q++) {
        int row = warp_n + q * 16 + b_row_l;
        brb[q] = row * 128;
        bxr[q] = row & 7;
    }

    float acc[4][4][4];
#pragma unroll
    for (int i = 0; i < 4; i++)
#pragma unroll
        for (int j = 0; j < 4; j++)
#pragma unroll
            for (int e = 0; e < 4; e++) acc[i][j][e] = 0.f;

    auto do_fill = [&](int s, uint32_t bufb) {
        int tap = s >> 3, ci0 = (s & 7) * 64;
        int dy = tap / 3, dx = tap - dy * 3;
        const size_t abase = (((size_t)(b * 66 + iy + dy)) * 66 + (ix + dx)) * CH + ci0;
        const size_t wbase = ((size_t)(co0 + frow)) * KTOT + tap * 512 + ci0;
#pragma unroll
        for (int i = 0; i < 4; i++) {
            int seg = fseg0 + i;
            uint32_t off = SWZ128((uint32_t)(frow * 128 + seg * 16));
            cp16(bufb + A_OFF + off, A + abase + seg * 8);
            cp16(bufb + BH_OFF + off, Wh + wbase + seg * 8);
            cp16(bufb + BL_OFF + off, Wl + wbase + seg * 8);
        }
        cp_commit();
    };

    do_fill(0, sb);

    for (int s = 0; s < NC; s++) {
        uint32_t bb = sb + (s & 1) * BUFSZ;
        if (s + 1 < NC) {
            do_fill(s + 1, sb + ((s + 1) & 1) * BUFSZ);
            cp_wait<1>();
        } else {
            cp_wait<0>();
        }
        __syncthreads();

#pragma unroll
        for (int ks = 0; ks < 4; ks++) {
            uint32_t a[4][4], bf[2][4];
            const int ca = ks * 2 + a_cs;
            const int cb = ks * 2 + b_cs;
#pragma unroll
            for (int mf = 0; mf < 4; mf++)
                ldsm4(a[mf], bb + A_OFF + arb[mf] + ((uint32_t)(ca ^ axr[mf]) << 4));
            // pass 1: A x Whi
#pragma unroll
            for (int q = 0; q < 2; q++)
                ldsm4(bf[q], bb + BH_OFF + brb[q] + ((uint32_t)(cb ^ bxr[q]) << 4));
#pragma unroll
            for (int mf = 0; mf < 4; mf++)
#pragma unroll
                for (int nf = 0; nf < 4; nf++)
                    mma16816(acc[mf][nf], a[mf], &bf[nf >> 1][(nf & 1) * 2]);
            // pass 2: A x Wlo (A frags reused)
#pragma unroll
            for (int q = 0; q < 2; q++)
                ldsm4(bf[q], bb + BL_OFF + brb[q] + ((uint32_t)(cb ^ bxr[q]) << 4));
#pragma unroll
            for (int mf = 0; mf < 4; mf++)
#pragma unroll
                for (int nf = 0; nf < 4; nf++)
                    mma16816(acc[mf][nf], a[mf], &bf[nf >> 1][(nf & 1) * 2]);
        }
        __syncthreads();
    }

    // ---- epilogue ----
    const float* dmod = g_d[L] + b * CH;
    const float* s1 = g_s[1] + b * CH;
    float dm[4][2], bv[4][2], nv[4][2], sv[4][2];
#pragma unroll
    for (int nf = 0; nf < 4; nf++)
#pragma unroll
        for (int j = 0; j < 2; j++) {
            int co = co0 + warp_n + nf * 8 + (lane & 3) * 2 + j;
            dm[nf][j] = dmod[co] * CONV_SCALE;
            bv[nf][j] = bias[co];
            nv[nf][j] = ns[co];
            sv[nf][j] = (L == 0) ? s1[co] : 1.f;
        }

#pragma unroll
    for (int mf = 0; mf < 4; mf++)
#pragma unroll
        for (int h = 0; h < 2; h++) {
            int m = warp_m + mf * 16 + (lane >> 2) + h * 8;
            int py = y0 + (m >> 6), px = m & 63;
            int p = py * 64 + px;
            float nz = noise[b * PIX + p];
#pragma unroll
            for (int nf = 0; nf < 4; nf++) {
                float v0 = acc[mf][nf][h * 2 + 0] * dm[nf][0] + bv[nf][0] + nv[nf][0] * nz;
                float v1 = acc[mf][nf][h * 2 + 1] * dm[nf][1] + bv[nf][1] + nv[nf][1] * nz;
                v0 = (v0 >= 0.f) ? v0 : LRELU_A * v0;
                v1 = (v1 >= 0.f) ? v1 : LRELU_A * v1;
                int co = co0 + warp_n + nf * 8 + (lane & 3) * 2;
                if (L == 0) {
                    __half h0 = __float2half_rn(v0 * sv[nf][0]);
                    __half h1 = __float2half_rn(v1 * sv[nf][1]);
                    size_t addr = (((size_t)(b * 66 + py + 1)) * 66 + (px + 1)) * CH + co;
                    *reinterpret_cast<uint32_t*>(&g_a1[addr]) = packh2(h0, h1);
                } else {
                    Yext[((size_t)b * CH + co) * PIX + p] = v0;
                    Yext[((size_t)b * CH + co + 1) * PIX + p] = v1;
                }
            }
        }
}

// ---------------- to_rgb: grid (64, B_), 256 thr: 64 px x 4 ci-slices ----------------
__global__ void torgb_kernel(const float* __restrict__ h, const float* __restrict__ rgb_in,
                             const float* __restrict__ rgb_w, const float* __restrict__ rgb_b,
                             float* __restrict__ out) {
    int b = blockIdx.y;
    int tid = threadIdx.x;
    int px = tid & 63, slice = tid >> 6;
    int p = blockIdx.x * 64 + px;
    __shared__ float wr[3][CH];
    __shared__ float red[3][4][64];
    const float* sr = g_s[2] + b * CH;
    for (int i = tid; i < 3 * CH; i += 256) {
        int c = i >> 9, ci = i & 511;
        wr[c][ci] = rgb_w[c * CH + ci] * RGB_SCALE * sr[ci];
    }
    __syncthreads();

    float a0 = 0.f, a1 = 0.f, a2 = 0.f;
    const float* hp = h + (size_t)b * CH * PIX + p;
#pragma unroll 8
    for (int ci = slice * 128; ci < slice * 128 + 128; ci++) {
        float hv = hp[(size_t)ci * PIX];
        a0 += wr[0][ci] * hv;
        a1 += wr[1][ci] * hv;
        a2 += wr[2][ci] * hv;
    }
    red[0][slice][px] = a0;
    red[1][slice][px] = a1;
    red[2][slice][px] = a2;
    __syncthreads();
    if (slice == 0) {
        int Y = p >> 6, X = p & 63;
        int y0, y1, x0, x1; float wy0, wy1, wx0, wx1;
        up_wts(Y, y0, y1, wy0, wy1);
        up_wts(X, x0, x1, wx0, wx1);
#pragma unroll
        for (int c = 0; c < 3; c++) {
            float acc = red[c][0][px] + red[c][1][px] + red[c][2][px] + red[c][3][px];
            const float* rin = rgb_in + ((size_t)b * 3 + c) * 1024;
            float rup = wy0 * (wx0 * rin[y0 * 32 + x0] + wx1 * rin[y0 * 32 + x1]) +
                        wy1 * (wx0 * rin[y1 * 32 + x0] + wx1 * rin[y1 * 32 + x1]);
            out[((size_t)b * 3 + c) * PIX + p] = rup + acc + rgb_b[c];
        }
    }
}

// ---------------- launch ----------------
extern "C" void kernel_launch(void* const* d_in, const int* in_sizes, int n_in,
                              void* d_out, int out_size) {
    const float* maps    = (const float*)d_in[0];
    const float* w       = (const float*)d_in[1];
    const float* rgb     = (const float*)d_in[2];
    const float* noise0  = (const float*)d_in[3];
    const float* noise1  = (const float*)d_in[4];
    const float* conv0_w = (const float*)d_in[5];
    const float* conv0_b = (const float*)d_in[6];
    const float* ms0_w   = (const float*)d_in[7];
    const float* ms0_b   = (const float*)d_in[8];
    const float* ns0     = (const float*)d_in[9];
    const float* conv1_w = (const float*)d_in[10];
    const float* conv1_b = (const float*)d_in[11];
    const float* ms1_w   = (const float*)d_in[12];
    const float* ms1_b   = (const float*)d_in[13];
    const float* ns1     = (const float*)d_in[14];
    const float* rgb_w   = (const float*)d_in[15];
    const float* rgb_b   = (const float*)d_in[16];
    const float* msr_w   = (const float*)d_in[17];
    const float* msr_b   = (const float*)d_in[18];

    float* out = (float*)d_out;
    float* hout = out + (size_t)B_ * 3 * PIX;

    cudaFuncSetAttribute(conv_mma<0>, cudaFuncAttributeMaxDynamicSharedMemorySize, SMEM_CONV);
    cudaFuncSetAttribute(conv_mma<1>, cudaFuncAttributeMaxDynamicSharedMemorySize, SMEM_CONV);

    style_kernel<<<dim3(8, B_, 3), 256>>>(w, ms0_w, ms0_b, ms1_w, ms1_b, msr_w, msr_b);
    wprep_kernel<<<dim3(512, 2), 256>>>(conv0_w, conv1_w);
    demod_kernel<<<dim3(8, B_, 2), 256>>>();
    upmod_kernel<<<dim3(64, 8, B_), 256>>>(maps);
    conv_mma<0><<<dim3(4, 32, B_), 256, SMEM_CONV>>>(conv0_b, ns0, noise0, nullptr);
    conv_mma<1><<<dim3(4, 32, B_), 256, SMEM_CONV>>>(conv1_b, ns1, noise1, hout);
    torgb_kernel<<<dim3(64, B_), 256>>>(hout, rgb, rgb_w, rgb_b, out);
}

// round 17
// speedup vs baseline: 5.3467x; 1.6620x over previous
#include <cuda_runtime.h>
#include <cuda_fp16.h>
#include <cstdint>

#define B_ 4
#define CH 512
#define PIX 4096            // 64*64
#define KTOT 4608           // 9*512
#define CONV_SCALE 0.020428760f
#define MS_SCALE   0.044194174f
#define RGB_SCALE  0.086419101f
#define LRELU_A    0.2f

// ---------------- device scratch (static; zero-init => pads stay zero) ----------------
__device__ __half g_a0[B_ * 66 * 66 * CH];       // fp16 activations, NHWC w/ 1px halo
__device__ __half g_a1[B_ * 66 * 66 * CH];
__device__ __half g_w16[2][CH * KTOT];           // [layer][co*4608 + tap*512 + ci] fp16
__device__ float g_wsqT[2][CH * CH];             // [layer][ci*CH + co]
__device__ float g_s[3][B_ * CH];                // styles s0, s1, sr
__device__ float g_d[2][B_ * CH];                // demod factors

// ---------------- helpers ----------------
__device__ __forceinline__ uint32_t smem_u32(const void* p) {
    uint32_t a;
    asm("{ .reg .u64 t; cvta.to.shared.u64 t, %1; cvt.u32.u64 %0, t; }" : "=r"(a) : "l"(p));
    return a;
}
#define SWZ128(x) ((x) ^ (((x) >> 3) & 0x70))

__device__ __forceinline__ void cp16(uint32_t dst, const void* src) {
    asm volatile("cp.async.cg.shared.global [%0], [%1], 16;" :: "r"(dst), "l"(src));
}
__device__ __forceinline__ void cp_commit() { asm volatile("cp.async.commit_group;" ::: "memory"); }
template <int N>
__device__ __forceinline__ void cp_wait() {
    asm volatile("cp.async.wait_group %0;" :: "n"(N) : "memory");
}

__device__ __forceinline__ void ldsm4(uint32_t* r, uint32_t addr) {
    asm volatile("ldmatrix.sync.aligned.m8n8.x4.shared.b16 {%0,%1,%2,%3}, [%4];"
                 : "=r"(r[0]), "=r"(r[1]), "=r"(r[2]), "=r"(r[3]) : "r"(addr));
}
__device__ __forceinline__ void mma16816(float* d, const uint32_t* a, const uint32_t* b) {
    asm volatile(
        "mma.sync.aligned.m16n8k16.row.col.f32.f16.f16.f32 "
        "{%0,%1,%2,%3}, {%4,%5,%6,%7}, {%8,%9}, {%0,%1,%2,%3};"
        : "+f"(d[0]), "+f"(d[1]), "+f"(d[2]), "+f"(d[3])
        : "r"(a[0]), "r"(a[1]), "r"(a[2]), "r"(a[3]), "r"(b[0]), "r"(b[1]));
}

// bilinear-2x (half-pixel, edge-clamped) weights
__device__ __forceinline__ void up_wts(int c, int& j0, int& j1, float& w0, float& w1) {
    int i = c >> 1;
    if (c & 1) { j0 = i; j1 = (i + 1 < 32) ? i + 1 : 31; w0 = 0.75f; w1 = 0.25f; }
    else       { j0 = (i > 0) ? i - 1 : 0; j1 = i;       w0 = 0.25f; w1 = 0.75f; }
}

__device__ __forceinline__ uint32_t packh2(__half a, __half b) {
    uint16_t ua = *reinterpret_cast<uint16_t*>(&a);
    uint16_t ub = *reinterpret_cast<uint16_t*>(&b);
    return (uint32_t)ua | ((uint32_t)ub << 16);
}

// ---------------- styles ----------------
__global__ void style_kernel(const float* __restrict__ w,
                             const float* __restrict__ m0w, const float* __restrict__ m0b,
                             const float* __restrict__ m1w, const float* __restrict__ m1b,
                             const float* __restrict__ mrw, const float* __restrict__ mrb) {
    int which = blockIdx.z, b = blockIdx.y;
    int cib = blockIdx.x * 64;
    const float* mw = (which == 0) ? m0w : (which == 1) ? m1w : mrw;
    const float* mb = (which == 0) ? m0b : (which == 1) ? m1b : mrb;
    __shared__ float ws[CH];
    int tid = threadIdx.x, lane = tid & 31, warp = tid >> 5;
    for (int i = tid; i < CH; i += 256) ws[i] = w[b * CH + i];
    __syncthreads();
#pragma unroll
    for (int q = 0; q < 8; q++) {
        int ci = cib + warp + q * 8;
        const float* row = mw + (size_t)ci * CH;
        float a = 0.f;
#pragma unroll 4
        for (int j = lane; j < CH; j += 32) a += ws[j] * row[j];
#pragma unroll
        for (int o = 16; o; o >>= 1) a += __shfl_xor_sync(~0u, a, o);
        if (lane == 0) g_s[which][b * CH + ci] = a * MS_SCALE + mb[ci];
    }
}

// ---------------- weight prep: transpose to [co][tap*512+ci], fp16; fused wsq ----------
__global__ void wprep_kernel(const float* __restrict__ w0, const float* __restrict__ w1) {
    int layer = blockIdx.y, co = blockIdx.x, tid = threadIdx.x;
    const float* src = (layer ? w1 : w0) + (size_t)co * KTOT;
    __shared__ float buf[KTOT];
    for (int i = tid; i < KTOT; i += 256) buf[i] = src[i];
    __syncthreads();
    __half* dst = g_w16[layer] + (size_t)co * KTOT;
    for (int i = tid; i < KTOT; i += 256) {
        int kk = i >> 9, ci = i & 511;
        dst[i] = __float2half_rn(buf[ci * 9 + kk]);
    }
    for (int ci = tid; ci < CH; ci += 256) {
        float acc = 0.f;
#pragma unroll
        for (int k = 0; k < 9; k++) { float v = buf[ci * 9 + k]; acc += v * v; }
        g_wsqT[layer][ci * CH + co] = acc;
    }
}

// ---------------- demod ----------------
__global__ void demod_kernel() {
    int layer = blockIdx.z, b = blockIdx.y;
    int co = blockIdx.x * 64 + (threadIdx.x & 63);
    int slice = threadIdx.x >> 6;
    __shared__ float s2[CH];
    __shared__ float red[256];
    const float* sl = g_s[layer] + b * CH;
    for (int i = threadIdx.x; i < CH; i += 256) { float v = sl[i]; s2[i] = v * v; }
    __syncthreads();
    const float* wt = g_wsqT[layer];
    float acc = 0.f;
#pragma unroll 8
    for (int ci = slice * 128; ci < slice * 128 + 128; ci++) acc += wt[ci * CH + co] * s2[ci];
    red[threadIdx.x] = acc;
    __syncthreads();
    if (slice == 0) {
        float t = red[threadIdx.x] + red[threadIdx.x + 64] + red[threadIdx.x + 128] +
                  red[threadIdx.x + 192];
        g_d[layer][b * CH + co] = rsqrtf(t * (CONV_SCALE * CONV_SCALE) + 1e-8f);
    }
}

// ---------------- upsample 2x + modulate s0 -> NHWC padded fp16 ----------------
// grid (64 y, 8 cic, B_)
__global__ void upmod_kernel(const float* __restrict__ maps) {
    int y = blockIdx.x, cic = blockIdx.y, b = blockIdx.z, tid = threadIdx.x;
    int y0, y1; float wy0, wy1;
    up_wts(y, y0, y1, wy0, wy1);
    __shared__ float s[2][64][33];
    for (int idx = tid; idx < 4096; idx += 256) {
        int r = idx >> 11, ci = (idx >> 5) & 63, xc = idx & 31;
        int ys = r ? y1 : y0;
        s[r][ci][xc] = maps[(((size_t)b * CH + cic * 64 + ci) * 32 + ys) * 32 + xc];
    }
    __syncthreads();
    int ci = tid & 63, xq = tid >> 6;
    float sv = g_s[0][b * CH + cic * 64 + ci];
#pragma unroll
    for (int xx = xq; xx < 64; xx += 4) {
        int x0, x1; float wx0, wx1;
        up_wts(xx, x0, x1, wx0, wx1);
        float v = wy0 * (wx0 * s[0][ci][x0] + wx1 * s[0][ci][x1]) +
                  wy1 * (wx0 * s[1][ci][x0] + wx1 * s[1][ci][x1]);
        size_t addr = (((size_t)(b * 66 + y + 1)) * 66 + (xx + 1)) * CH + cic * 64 + ci;
        g_a0[addr] = __float2half_rn(v * sv);
    }
}

// ---------------- HMMA conv: CTA 128px x 128co, warp m64n32, K-chunk 64 ----------------
// single-pass fp16 weights, 3-stage cp.async pipeline, one barrier per chunk
#define NC 72                  // 9 taps * 8 ci-chunks of 64
#define A_OFF 0
#define B_OFF 16384
#define BUFSZ 32768
#define SMEM_CONV (3 * BUFSZ)

template <int L>
__global__ void __launch_bounds__(256, 2) conv_mma(const float* __restrict__ bias,
                                                   const float* __restrict__ ns,
                                                   const float* __restrict__ noise,
                                                   float* __restrict__ Yext) {
    extern __shared__ __align__(1024) char smem_raw[];
    const uint32_t sb = smem_u32(smem_raw);

    const int tid = threadIdx.x;
    const int lane = tid & 31;
    const int wid = tid >> 5;
    const int b = blockIdx.z;
    const int y0 = blockIdx.y * 2;        // 2 image rows = 128 px
    const int co0 = blockIdx.x * 128;

    const __half* A = (L == 0) ? g_a0 : g_a1;
    const __half* W = g_w16[L];

    // ---- fill coordinates: 2 threads per row, 4x16B segments each ----
    const int frow = tid >> 1;
    const int fseg0 = (tid & 1) * 4;
    const int iy = y0 + (frow >> 6);
    const int ix = frow & 63;

    // ---- ldmatrix address prep ----
    const int warp_m = (wid & 1) * 64;
    const int warp_n = (wid >> 1) * 32;
    const int a_row_l = ((lane >> 3) & 1) * 8 + (lane & 7);
    const int a_cs = lane >> 4;               // 0/1
    const int b_row_l = ((lane >> 4) & 1) * 8 + (lane & 7);
    const int b_cs = (lane >> 3) & 1;

    uint32_t arb[4]; int axr[4];
#pragma unroll
    for (int mf = 0; mf < 4; mf++) {
        int row = warp_m + mf * 16 + a_row_l;
        arb[mf] = row * 128;
        axr[mf] = row & 7;
    }
    uint32_t brb[2]; int bxr[2];
#pragma unroll
    for (int q = 0; q < 2; q++) {
        int row = warp_n + q * 16 + b_row_l;
        brb[q] = row * 128;
        bxr[q] = row & 7;
    }

    float acc[4][4][4];
#pragma unroll
    for (int i = 0; i < 4; i++)
#pragma unroll
        for (int j = 0; j < 4; j++)
#pragma unroll
            for (int e = 0; e < 4; e++) acc[i][j][e] = 0.f;

    auto do_fill = [&](int s) {
        uint32_t bufb = sb + (uint32_t)(s % 3) * BUFSZ;
        int tap = s >> 3, ci0 = (s & 7) * 64;
        int dy = tap / 3, dx = tap - dy * 3;
        const size_t abase = (((size_t)(b * 66 + iy + dy)) * 66 + (ix + dx)) * CH + ci0;
        const size_t wbase = ((size_t)(co0 + frow)) * KTOT + tap * 512 + ci0;
#pragma unroll
        for (int i = 0; i < 4; i++) {
            int seg = fseg0 + i;
            uint32_t off = SWZ128((uint32_t)(frow * 128 + seg * 16));
            cp16(bufb + A_OFF + off, A + abase + seg * 8);
            cp16(bufb + B_OFF + off, W + wbase + seg * 8);
        }
        cp_commit();
    };

    do_fill(0);
    do_fill(1);

    for (int s = 0; s < NC; s++) {
        uint32_t bb = sb + (uint32_t)(s % 3) * BUFSZ;
        if (s + 1 < NC) cp_wait<1>(); else cp_wait<0>();
        __syncthreads();
        if (s + 2 < NC) do_fill(s + 2);

#pragma unroll
        for (int ks = 0; ks < 4; ks++) {
            uint32_t a[4][4], bf[2][4];
            const int ca = ks * 2 + a_cs;
            const int cb = ks * 2 + b_cs;
#pragma unroll
            for (int mf = 0; mf < 4; mf++)
                ldsm4(a[mf], bb + A_OFF + arb[mf] + ((uint32_t)(ca ^ axr[mf]) << 4));
#pragma unroll
            for (int q = 0; q < 2; q++)
                ldsm4(bf[q], bb + B_OFF + brb[q] + ((uint32_t)(cb ^ bxr[q]) << 4));
#pragma unroll
            for (int mf = 0; mf < 4; mf++)
#pragma unroll
                for (int nf = 0; nf < 4; nf++)
                    mma16816(acc[mf][nf], a[mf], &bf[nf >> 1][(nf & 1) * 2]);
        }
    }

    // ---- epilogue ----
    const float* dmod = g_d[L] + b * CH;
    const float* s1 = g_s[1] + b * CH;
    float dm[4][2], bv[4][2], nv[4][2], sv[4][2];
#pragma unroll
    for (int nf = 0; nf < 4; nf++)
#pragma unroll
        for (int j = 0; j < 2; j++) {
            int co = co0 + warp_n + nf * 8 + (lane & 3) * 2 + j;
            dm[nf][j] = dmod[co] * CONV_SCALE;
            bv[nf][j] = bias[co];
            nv[nf][j] = ns[co];
            sv[nf][j] = (L == 0) ? s1[co] : 1.f;
        }

#pragma unroll
    for (int mf = 0; mf < 4; mf++)
#pragma unroll
        for (int h = 0; h < 2; h++) {
            int m = warp_m + mf * 16 + (lane >> 2) + h * 8;
            int py = y0 + (m >> 6), px = m & 63;
            int p = py * 64 + px;
            float nz = noise[b * PIX + p];
#pragma unroll
            for (int nf = 0; nf < 4; nf++) {
                float v0 = acc[mf][nf][h * 2 + 0] * dm[nf][0] + bv[nf][0] + nv[nf][0] * nz;
                float v1 = acc[mf][nf][h * 2 + 1] * dm[nf][1] + bv[nf][1] + nv[nf][1] * nz;
                v0 = (v0 >= 0.f) ? v0 : LRELU_A * v0;
                v1 = (v1 >= 0.f) ? v1 : LRELU_A * v1;
                int co = co0 + warp_n + nf * 8 + (lane & 3) * 2;
                if (L == 0) {
                    __half h0 = __float2half_rn(v0 * sv[nf][0]);
                    __half h1 = __float2half_rn(v1 * sv[nf][1]);
                    size_t addr = (((size_t)(b * 66 + py + 1)) * 66 + (px + 1)) * CH + co;
                    *reinterpret_cast<uint32_t*>(&g_a1[addr]) = packh2(h0, h1);
                } else {
                    Yext[((size_t)b * CH + co) * PIX + p] = v0;
                    Yext[((size_t)b * CH + co + 1) * PIX + p] = v1;
                }
            }
        }
}

// ---------------- to_rgb: grid (64, B_), 256 thr: 64 px x 4 ci-slices ----------------
__global__ void torgb_kernel(const float* __restrict__ h, const float* __restrict__ rgb_in,
                             const float* __restrict__ rgb_w, const float* __restrict__ rgb_b,
                             float* __restrict__ out) {
    int b = blockIdx.y;
    int tid = threadIdx.x;
    int px = tid & 63, slice = tid >> 6;
    int p = blockIdx.x * 64 + px;
    __shared__ float wr[3][CH];
    __shared__ float red[3][4][64];
    const float* sr = g_s[2] + b * CH;
    for (int i = tid; i < 3 * CH; i += 256) {
        int c = i >> 9, ci = i & 511;
        wr[c][ci] = rgb_w[c * CH + ci] * RGB_SCALE * sr[ci];
    }
    __syncthreads();

    float a0 = 0.f, a1 = 0.f, a2 = 0.f;
    const float* hp = h + (size_t)b * CH * PIX + p;
#pragma unroll 8
    for (int ci = slice * 128; ci < slice * 128 + 128; ci++) {
        float hv = hp[(size_t)ci * PIX];
        a0 += wr[0][ci] * hv;
        a1 += wr[1][ci] * hv;
        a2 += wr[2][ci] * hv;
    }
    red[0][slice][px] = a0;
    red[1][slice][px] = a1;
    red[2][slice][px] = a2;
    __syncthreads();
    if (slice == 0) {
        int Y = p >> 6, X = p & 63;
        int y0, y1, x0, x1; float wy0, wy1, wx0, wx1;
        up_wts(Y, y0, y1, wy0, wy1);
        up_wts(X, x0, x1, wx0, wx1);
#pragma unroll
        for (int c = 0; c < 3; c++) {
            float acc = red[c][0][px] + red[c][1][px] + red[c][2][px] + red[c][3][px];
            const float* rin = rgb_in + ((size_t)b * 3 + c) * 1024;
            float rup = wy0 * (wx0 * rin[y0 * 32 + x0] + wx1 * rin[y0 * 32 + x1]) +
                        wy1 * (wx0 * rin[y1 * 32 + x0] + wx1 * rin[y1 * 32 + x1]);
            out[((size_t)b * 3 + c) * PIX + p] = rup + acc + rgb_b[c];
        }
    }
}

// ---------------- launch ----------------
extern "C" void kernel_launch(void* const* d_in, const int* in_sizes, int n_in,
                              void* d_out, int out_size) {
    const float* maps    = (const float*)d_in[0];
    const float* w       = (const float*)d_in[1];
    const float* rgb     = (const float*)d_in[2];
    const float* noise0  = (const float*)d_in[3];
    const float* noise1  = (const float*)d_in[4];
    const float* conv0_w = (const float*)d_in[5];
    const float* conv0_b = (const float*)d_in[6];
    const float* ms0_w   = (const float*)d_in[7];
    const float* ms0_b   = (const float*)d_in[8];
    const float* ns0     = (const float*)d_in[9];
    const float* conv1_w = (const float*)d_in[10];
    const float* conv1_b = (const float*)d_in[11];
    const float* ms1_w   = (const float*)d_in[12];
    const float* ms1_b   = (const float*)d_in[13];
    const float* ns1     = (const float*)d_in[14];
    const float* rgb_w   = (const float*)d_in[15];
    const float* rgb_b   = (const float*)d_in[16];
    const float* msr_w   = (const float*)d_in[17];
    const float* msr_b   = (const float*)d_in[18];

    float* out = (float*)d_out;
    float* hout = out + (size_t)B_ * 3 * PIX;

    cudaFuncSetAttribute(conv_mma<0>, cudaFuncAttributeMaxDynamicSharedMemorySize, SMEM_CONV);
    cudaFuncSetAttribute(conv_mma<1>, cudaFuncAttributeMaxDynamicSharedMemorySize, SMEM_CONV);

    style_kernel<<<dim3(8, B_, 3), 256>>>(w, ms0_w, ms0_b, ms1_w, ms1_b, msr_w, msr_b);
    wprep_kernel<<<dim3(512, 2), 256>>>(conv0_w, conv1_w);
    demod_kernel<<<dim3(8, B_, 2), 256>>>();
    upmod_kernel<<<dim3(64, 8, B_), 256>>>(maps);
    conv_mma<0><<<dim3(4, 32, B_), 256, SMEM_CONV>>>(conv0_b, ns0, noise0, nullptr);
    conv_mma<1><<<dim3(4, 32, B_), 256, SMEM_CONV>>>(conv1_b, ns1, noise1, hout);
    torgb_kernel<<<dim3(64, B_), 256>>>(hout, rgb, rgb_w, rgb_b, out);
}